// round 7
// baseline (speedup 1.0000x reference)
#include <cuda_runtime.h>
#include <mma.h>
#include <cstdint>

using namespace nvcuda;

#define NN 100000
#define NE 600000
#define SCAN_B 1024
#define NBLK ((NN + SCAN_B - 1) / SCAN_B)   // 98

// Scratch (device globals: no allocation allowed anywhere).
__device__ __align__(16) int   g_deg[NN];
__device__ __align__(16) int   g_cnt[NN];
__device__ __align__(16) int   g_rowstart[NN + 1];
__device__ __align__(16) int   g_blocksum[NBLK];
__device__ __align__(16) int   g_csr[NE];
__device__ __align__(16) float g_dinv[NN];
__device__ __align__(16) float g_g1[NN * 128];  // dinv * (x @ W1)
__device__ __align__(16) float g_h1[NN * 128];  // relu(dinv*agg + b1)
__device__ __align__(16) float g_g2[NN * 64];   // dinv * (h1 @ W2)
__device__ int g_is64;                          // edge index storage layout flag

__device__ __forceinline__ int edge_src(const int* ei, int e) {
    return g_is64 ? (int)((const long long*)ei)[e] : ei[e];
}
__device__ __forceinline__ int edge_dst(const int* ei, int e) {
    return g_is64 ? (int)((const long long*)ei)[NE + e] : ei[NE + e];
}

// ---------------------------------------------------------------- detect
__global__ void k_detect(const int* __restrict__ ei) {
    __shared__ int flag;
    if (threadIdx.x == 0) flag = 0;
    __syncthreads();
    int any = 0;
    for (int i = threadIdx.x; i < 4096; i += 256)
        if (ei[2 * i + 1] != 0) any = 1;
    if (any) flag = 1;
    __syncthreads();
    if (threadIdx.x == 0) g_is64 = flag ? 0 : 1;
}

// ---------------------------------------------------------------- init
__global__ void k_zero() {
    int i = blockIdx.x * blockDim.x + threadIdx.x;
    if (i < NN) { g_deg[i] = 0; g_cnt[i] = 0; }
}

__global__ void k_count(const int* __restrict__ ei) {
    int e = blockIdx.x * blockDim.x + threadIdx.x;
    if (e < NE) {
        int d = edge_dst(ei, e);
        if (d >= 0 && d < NN) atomicAdd(&g_deg[d], 1);
    }
}

__global__ void k_dinv() {
    int i = blockIdx.x * blockDim.x + threadIdx.x;
    if (i < NN) g_dinv[i] = rsqrtf((float)(g_deg[i] + 1));
}

// ---------------------------------------------------------------- scan
__global__ void __launch_bounds__(SCAN_B) k_scan_local() {
    __shared__ int s[SCAN_B];
    int tid = threadIdx.x;
    int gid = blockIdx.x * SCAN_B + tid;
    int v = (gid < NN) ? g_deg[gid] : 0;
    s[tid] = v;
    __syncthreads();
#pragma unroll
    for (int off = 1; off < SCAN_B; off <<= 1) {
        int t = (tid >= off) ? s[tid - off] : 0;
        __syncthreads();
        s[tid] += t;
        __syncthreads();
    }
    if (gid < NN) g_rowstart[gid] = s[tid] - v;
    if (tid == SCAN_B - 1) g_blocksum[blockIdx.x] = s[tid];
}

__global__ void k_scan_blocks() {
    __shared__ int s[NBLK];
    int tid = threadIdx.x;
    if (tid < NBLK) s[tid] = g_blocksum[tid];
    __syncthreads();
    if (tid == 0) {
        int run = 0;
        for (int i = 0; i < NBLK; i++) { int t = s[i]; s[i] = run; run += t; }
        g_rowstart[NN] = run;
    }
    __syncthreads();
    if (tid < NBLK) g_blocksum[tid] = s[tid];
}

__global__ void __launch_bounds__(SCAN_B) k_scan_add() {
    int gid = blockIdx.x * SCAN_B + threadIdx.x;
    if (gid < NN) g_rowstart[gid] += g_blocksum[blockIdx.x];
}

// ---------------------------------------------------------------- CSR fill
__global__ void k_fill(const int* __restrict__ ei) {
    int e = blockIdx.x * blockDim.x + threadIdx.x;
    if (e >= NE) return;
    int s = edge_src(ei, e);
    int d = edge_dst(ei, e);
    if (s < 0 || s >= NN || d < 0 || d >= NN) return;
    int pos = g_rowstart[d] + atomicAdd(&g_cnt[d], 1);
    g_csr[pos] = s;
}

// ---------------------------------------------------------------- GEMM1 (TF32 tensor cores)
// g1 = dinv ⊙ (x @ W1).  Block tile 128x128, K=128 resident. 8 warps: 2(m) x 4(n),
// warp tile 64x32 = 4x2 wmma m16n16k8 tiles.
__global__ void __launch_bounds__(256) k_gemm1(const float* __restrict__ x,
                                               const float* __restrict__ W) {
    extern __shared__ float sm[];
    float* sX = sm;              // 128*128
    float* sW = sm + 128 * 128;  // 128*128
    int tid = threadIdx.x;
    int row0 = blockIdx.x * 128;

    for (int i = tid; i < 128 * 128 / 4; i += 256)
        ((float4*)sW)[i] = ((const float4*)W)[i];
    for (int i = tid; i < 128 * 128 / 4; i += 256) {
        int r = i >> 5;
        int gr = row0 + r;
        ((float4*)sX)[i] = (gr < NN) ? ((const float4*)x)[gr * 32 + (i & 31)]
                                     : make_float4(0.f, 0.f, 0.f, 0.f);
    }
    __syncthreads();

    int wid = tid >> 5;
    int wm = wid & 1;    // m offset 64*wm
    int wn = wid >> 1;   // n offset 32*wn

    wmma::fragment<wmma::accumulator, 16, 16, 8, float> acc[4][2];
#pragma unroll
    for (int i = 0; i < 4; i++)
#pragma unroll
        for (int j = 0; j < 2; j++) wmma::fill_fragment(acc[i][j], 0.f);

#pragma unroll
    for (int k = 0; k < 128; k += 8) {
        wmma::fragment<wmma::matrix_a, 16, 16, 8, wmma::precision::tf32, wmma::row_major> a[4];
        wmma::fragment<wmma::matrix_b, 16, 16, 8, wmma::precision::tf32, wmma::row_major> b[2];
#pragma unroll
        for (int i = 0; i < 4; i++) {
            wmma::load_matrix_sync(a[i], sX + (wm * 64 + 16 * i) * 128 + k, 128);
#pragma unroll
            for (int t = 0; t < a[i].num_elements; t++)
                a[i].x[t] = wmma::__float_to_tf32(a[i].x[t]);
        }
#pragma unroll
        for (int j = 0; j < 2; j++) {
            wmma::load_matrix_sync(b[j], sW + k * 128 + wn * 32 + 16 * j, 128);
#pragma unroll
            for (int t = 0; t < b[j].num_elements; t++)
                b[j].x[t] = wmma::__float_to_tf32(b[j].x[t]);
        }
#pragma unroll
        for (int i = 0; i < 4; i++)
#pragma unroll
            for (int j = 0; j < 2; j++)
                wmma::mma_sync(acc[i][j], a[i], b[j], acc[i][j]);
    }

    __syncthreads();   // done reading sX/sW; reuse sX as staging
#pragma unroll
    for (int i = 0; i < 4; i++)
#pragma unroll
        for (int j = 0; j < 2; j++)
            wmma::store_matrix_sync(sX + (wm * 64 + 16 * i) * 128 + wn * 32 + 16 * j,
                                    acc[i][j], 128, wmma::mem_row_major);
    __syncthreads();

    for (int i = tid; i < 128 * 32; i += 256) {
        int r = i >> 5;
        int gr = row0 + r;
        if (gr < NN) {
            float s = g_dinv[gr];
            float4 v = ((float4*)sX)[i];
            ((float4*)g_g1)[gr * 32 + (i & 31)] =
                make_float4(s * v.x, s * v.y, s * v.z, s * v.w);
        }
    }
}

// ---------------------------------------------------------------- aggregate1
__global__ void __launch_bounds__(256) k_agg1(const float* __restrict__ b1) {
    int node = (blockIdx.x * 256 + threadIdx.x) >> 5;
    int lane = threadIdx.x & 31;
    if (node >= NN) return;
    int beg = g_rowstart[node];
    int end = g_rowstart[node + 1];
    float4 acc = ((const float4*)g_g1)[node * 32 + lane];
    for (int i = beg; i < end; i++) {
        int s = g_csr[i];
        float4 v = ((const float4*)g_g1)[s * 32 + lane];
        acc.x += v.x; acc.y += v.y; acc.z += v.z; acc.w += v.w;
    }
    float dn = g_dinv[node];
    float4 o;
    o.x = fmaxf(fmaf(dn, acc.x, __ldg(&b1[lane * 4 + 0])), 0.f);
    o.y = fmaxf(fmaf(dn, acc.y, __ldg(&b1[lane * 4 + 1])), 0.f);
    o.z = fmaxf(fmaf(dn, acc.z, __ldg(&b1[lane * 4 + 2])), 0.f);
    o.w = fmaxf(fmaf(dn, acc.w, __ldg(&b1[lane * 4 + 3])), 0.f);
    ((float4*)g_h1)[node * 32 + lane] = o;
}

// ---------------------------------------------------------------- GEMM2 (TF32 tensor cores)
// g2 = dinv ⊙ (h1 @ W2). Block tile 128x64. 8 warps: 4(m) x 2(n), warp tile 32x32.
__global__ void __launch_bounds__(256) k_gemm2(const float* __restrict__ W2) {
    extern __shared__ float sm[];
    float* sX = sm;              // 128*128
    float* sW = sm + 128 * 128;  // 128*64
    int tid = threadIdx.x;
    int row0 = blockIdx.x * 128;

    for (int i = tid; i < 128 * 64 / 4; i += 256)
        ((float4*)sW)[i] = ((const float4*)W2)[i];
    for (int i = tid; i < 128 * 128 / 4; i += 256) {
        int r = i >> 5;
        int gr = row0 + r;
        ((float4*)sX)[i] = (gr < NN) ? ((const float4*)g_h1)[gr * 32 + (i & 31)]
                                     : make_float4(0.f, 0.f, 0.f, 0.f);
    }
    __syncthreads();

    int wid = tid >> 5;
    int wm = wid & 3;    // m offset 32*wm
    int wn = wid >> 2;   // n offset 32*wn

    wmma::fragment<wmma::accumulator, 16, 16, 8, float> acc[2][2];
#pragma unroll
    for (int i = 0; i < 2; i++)
#pragma unroll
        for (int j = 0; j < 2; j++) wmma::fill_fragment(acc[i][j], 0.f);

#pragma unroll
    for (int k = 0; k < 128; k += 8) {
        wmma::fragment<wmma::matrix_a, 16, 16, 8, wmma::precision::tf32, wmma::row_major> a[2];
        wmma::fragment<wmma::matrix_b, 16, 16, 8, wmma::precision::tf32, wmma::row_major> b[2];
#pragma unroll
        for (int i = 0; i < 2; i++) {
            wmma::load_matrix_sync(a[i], sX + (wm * 32 + 16 * i) * 128 + k, 128);
#pragma unroll
            for (int t = 0; t < a[i].num_elements; t++)
                a[i].x[t] = wmma::__float_to_tf32(a[i].x[t]);
        }
#pragma unroll
        for (int j = 0; j < 2; j++) {
            wmma::load_matrix_sync(b[j], sW + k * 64 + wn * 32 + 16 * j, 64);
#pragma unroll
            for (int t = 0; t < b[j].num_elements; t++)
                b[j].x[t] = wmma::__float_to_tf32(b[j].x[t]);
        }
#pragma unroll
        for (int i = 0; i < 2; i++)
#pragma unroll
            for (int j = 0; j < 2; j++)
                wmma::mma_sync(acc[i][j], a[i], b[j], acc[i][j]);
    }

    __syncthreads();
#pragma unroll
    for (int i = 0; i < 2; i++)
#pragma unroll
        for (int j = 0; j < 2; j++)
            wmma::store_matrix_sync(sX + (wm * 32 + 16 * i) * 64 + wn * 32 + 16 * j,
                                    acc[i][j], 64, wmma::mem_row_major);
    __syncthreads();

    for (int i = tid; i < 128 * 16; i += 256) {
        int r = i >> 4;
        int gr = row0 + r;
        if (gr < NN) {
            float s = g_dinv[gr];
            float4 v = ((float4*)sX)[i];
            ((float4*)g_g2)[gr * 16 + (i & 15)] =
                make_float4(s * v.x, s * v.y, s * v.z, s * v.w);
        }
    }
}

// ---------------------------------------------------------------- aggregate2
__global__ void __launch_bounds__(256) k_agg2(const float* __restrict__ b2,
                                              float* __restrict__ out) {
    int t = blockIdx.x * 256 + threadIdx.x;
    int node = t >> 4;
    int l = t & 15;
    if (node >= NN) return;
    int beg = g_rowstart[node];
    int end = g_rowstart[node + 1];
    float4 acc = ((const float4*)g_g2)[node * 16 + l];
    for (int i = beg; i < end; i++) {
        int s = g_csr[i];
        float4 v = ((const float4*)g_g2)[s * 16 + l];
        acc.x += v.x; acc.y += v.y; acc.z += v.z; acc.w += v.w;
    }
    float dn = g_dinv[node];
    float4 o;
    o.x = fmaf(dn, acc.x, __ldg(&b2[l * 4 + 0]));
    o.y = fmaf(dn, acc.y, __ldg(&b2[l * 4 + 1]));
    o.z = fmaf(dn, acc.z, __ldg(&b2[l * 4 + 2]));
    o.w = fmaf(dn, acc.w, __ldg(&b2[l * 4 + 3]));
    ((float4*)out)[node * 16 + l] = o;
}

// ----------------------------------------------------------------
extern "C" void kernel_launch(void* const* d_in, const int* in_sizes, int n_in,
                              void* d_out, int out_size) {
    const float* x  = (const float*)d_in[0];
    const int*   ei = (const int*)d_in[1];
    const float* W1 = (const float*)d_in[2];
    const float* b1 = (const float*)d_in[3];
    const float* W2 = (const float*)d_in[4];
    const float* b2 = (const float*)d_in[5];
    float* out = (float*)d_out;

    const int smem1 = (128 * 128 + 128 * 128) * 4;  // 128 KB
    const int smem2 = (128 * 128 + 128 * 64) * 4;   // 96 KB
    cudaFuncSetAttribute(k_gemm1, cudaFuncAttributeMaxDynamicSharedMemorySize, smem1);
    cudaFuncSetAttribute(k_gemm2, cudaFuncAttributeMaxDynamicSharedMemorySize, smem2);

    k_detect<<<1, 256>>>(ei);
    k_zero <<<(NN + 255) / 256, 256>>>();
    k_count<<<(NE + 255) / 256, 256>>>(ei);
    k_scan_local <<<NBLK, SCAN_B>>>();
    k_scan_blocks<<<1, 128>>>();
    k_scan_add   <<<NBLK, SCAN_B>>>();
    k_dinv <<<(NN + 255) / 256, 256>>>();
    k_fill <<<(NE + 255) / 256, 256>>>(ei);

    k_gemm1<<<(NN + 127) / 128, 256, smem1>>>(x, W1);
    k_agg1 <<<(NN * 32 + 255) / 256, 256>>>(b1);

    k_gemm2<<<(NN + 127) / 128, 256, smem2>>>(W2);
    k_agg2 <<<(NN * 16 + 255) / 256, 256>>>(b2, out);
}

// round 9
// speedup vs baseline: 1.3348x; 1.3348x over previous
#include <cuda_runtime.h>
#include <cstdint>

#define NN 100000
#define NE 600000
#define SCAN_B 1024
#define NBLK ((NN + SCAN_B - 1) / SCAN_B)   // 98

// Scratch (device globals: no allocation allowed anywhere).
__device__ __align__(16) int   g_deg[NN];
__device__ __align__(16) int   g_cnt[NN];
__device__ __align__(16) int   g_rowstart[NN + 1];
__device__ __align__(16) int   g_blocksum[NBLK];
__device__ __align__(16) int   g_csr[NE];
__device__ __align__(16) float g_dinv[NN];
__device__ __align__(16) float g_g1[NN * 128];  // dinv * (x @ W1)
__device__ __align__(16) float g_h1[NN * 128];  // relu(dinv*agg + b1)
__device__ __align__(16) float g_g2[NN * 64];   // dinv * (h1 @ W2)
__device__ int g_is64;                          // edge index storage layout flag

__device__ __forceinline__ int edge_src(const int* ei, int e) {
    return g_is64 ? (int)((const long long*)ei)[e] : ei[e];
}
__device__ __forceinline__ int edge_dst(const int* ei, int e) {
    return g_is64 ? (int)((const long long*)ei)[NE + e] : ei[NE + e];
}

// ---- packed f32x2 helpers (Blackwell FFMA2 — only reachable via PTX) ----
__device__ __forceinline__ unsigned long long pk2(float a, float b) {
    unsigned long long r;
    asm("mov.b64 %0, {%1, %2};" : "=l"(r) : "f"(a), "f"(b));
    return r;
}
__device__ __forceinline__ void fma2(unsigned long long& d,
                                     unsigned long long a, unsigned long long b) {
    asm("fma.rn.f32x2 %0, %1, %2, %0;" : "+l"(d) : "l"(a), "l"(b));
}
__device__ __forceinline__ float2 upk2(unsigned long long v) {
    float2 f;
    asm("mov.b64 {%0, %1}, %2;" : "=f"(f.x), "=f"(f.y) : "l"(v));
    return f;
}

// ---------------------------------------------------------------- detect
__global__ void k_detect(const int* __restrict__ ei) {
    __shared__ int flag;
    if (threadIdx.x == 0) flag = 0;
    __syncthreads();
    int any = 0;
    for (int i = threadIdx.x; i < 4096; i += 256)
        if (ei[2 * i + 1] != 0) any = 1;
    if (any) flag = 1;
    __syncthreads();
    if (threadIdx.x == 0) g_is64 = flag ? 0 : 1;
}

// ---------------------------------------------------------------- init
__global__ void k_zero() {
    int i = blockIdx.x * blockDim.x + threadIdx.x;
    if (i < NN) { g_deg[i] = 0; g_cnt[i] = 0; }
}

__global__ void k_count(const int* __restrict__ ei) {
    int e = blockIdx.x * blockDim.x + threadIdx.x;
    if (e < NE) {
        int d = edge_dst(ei, e);
        if (d >= 0 && d < NN) atomicAdd(&g_deg[d], 1);
    }
}

__global__ void k_dinv() {
    int i = blockIdx.x * blockDim.x + threadIdx.x;
    if (i < NN) g_dinv[i] = rsqrtf((float)(g_deg[i] + 1));
}

// ---------------------------------------------------------------- scan
__global__ void __launch_bounds__(SCAN_B) k_scan_local() {
    __shared__ int s[SCAN_B];
    int tid = threadIdx.x;
    int gid = blockIdx.x * SCAN_B + tid;
    int v = (gid < NN) ? g_deg[gid] : 0;
    s[tid] = v;
    __syncthreads();
#pragma unroll
    for (int off = 1; off < SCAN_B; off <<= 1) {
        int t = (tid >= off) ? s[tid - off] : 0;
        __syncthreads();
        s[tid] += t;
        __syncthreads();
    }
    if (gid < NN) g_rowstart[gid] = s[tid] - v;
    if (tid == SCAN_B - 1) g_blocksum[blockIdx.x] = s[tid];
}

__global__ void k_scan_blocks() {
    __shared__ int s[NBLK];
    int tid = threadIdx.x;
    if (tid < NBLK) s[tid] = g_blocksum[tid];
    __syncthreads();
    if (tid == 0) {
        int run = 0;
        for (int i = 0; i < NBLK; i++) { int t = s[i]; s[i] = run; run += t; }
        g_rowstart[NN] = run;
    }
    __syncthreads();
    if (tid < NBLK) g_blocksum[tid] = s[tid];
}

__global__ void __launch_bounds__(SCAN_B) k_scan_add() {
    int gid = blockIdx.x * SCAN_B + threadIdx.x;
    if (gid < NN) g_rowstart[gid] += g_blocksum[blockIdx.x];
}

// ---------------------------------------------------------------- CSR fill
__global__ void k_fill(const int* __restrict__ ei) {
    int e = blockIdx.x * blockDim.x + threadIdx.x;
    if (e >= NE) return;
    int s = edge_src(ei, e);
    int d = edge_dst(ei, e);
    if (s < 0 || s >= NN || d < 0 || d >= NN) return;
    int pos = g_rowstart[d] + atomicAdd(&g_cnt[d], 1);
    g_csr[pos] = s;
}

// ---------------------------------------------------------------- GEMM1 (FFMA2)
// g1[i][j] = dinv[i] * sum_k x[i][k] * W1[k][j]
// 256 threads, 64-row tile, 128 cols. Thread (c=tid&31, r=tid>>5) does
// cols 4c..4c+3 (2 packed pairs) for rows r, r+8, ..., r+56.
__global__ void __launch_bounds__(256) k_gemm1(const float* __restrict__ x,
                                               const float* __restrict__ W) {
    extern __shared__ float sm[];
    float* sW = sm;              // 128*128
    float* sX = sm + 128 * 128;  // 64*128
    int tid = threadIdx.x;
    int row0 = blockIdx.x * 64;

    for (int i = tid; i < 128 * 128 / 4; i += 256)
        ((float4*)sW)[i] = ((const float4*)W)[i];
    for (int i = tid; i < 64 * 128 / 4; i += 256) {
        int r = i >> 5;
        int gr = row0 + r;
        ((float4*)sX)[i] = (gr < NN) ? ((const float4*)x)[gr * 32 + (i & 31)]
                                     : make_float4(0.f, 0.f, 0.f, 0.f);
    }
    __syncthreads();

    int c = tid & 31;
    int r = tid >> 5;
    unsigned long long acc[8][2];
#pragma unroll
    for (int i = 0; i < 8; i++) { acc[i][0] = pk2(0.f, 0.f); acc[i][1] = pk2(0.f, 0.f); }

#pragma unroll 4
    for (int k = 0; k < 128; k++) {
        float4 w = ((const float4*)sW)[k * 32 + c];
        unsigned long long w01 = pk2(w.x, w.y);
        unsigned long long w23 = pk2(w.z, w.w);
#pragma unroll
        for (int i = 0; i < 8; i++) {
            float xv = sX[(r + 8 * i) * 128 + k];
            unsigned long long xx = pk2(xv, xv);
            fma2(acc[i][0], xx, w01);
            fma2(acc[i][1], xx, w23);
        }
    }

#pragma unroll
    for (int i = 0; i < 8; i++) {
        int gr = row0 + r + 8 * i;
        if (gr < NN) {
            float s = g_dinv[gr];
            float2 p0 = upk2(acc[i][0]);
            float2 p1 = upk2(acc[i][1]);
            ((float4*)g_g1)[gr * 32 + c] =
                make_float4(s * p0.x, s * p0.y, s * p1.x, s * p1.y);
        }
    }
}

// ---------------------------------------------------------------- aggregate1
__global__ void __launch_bounds__(256) k_agg1(const float* __restrict__ b1) {
    int node = (blockIdx.x * 256 + threadIdx.x) >> 5;
    int lane = threadIdx.x & 31;
    if (node >= NN) return;
    int beg = g_rowstart[node];
    int end = g_rowstart[node + 1];
    float4 acc = ((const float4*)g_g1)[node * 32 + lane];
    for (int i = beg; i < end; i++) {
        int s = g_csr[i];
        float4 v = ((const float4*)g_g1)[s * 32 + lane];
        acc.x += v.x; acc.y += v.y; acc.z += v.z; acc.w += v.w;
    }
    float dn = g_dinv[node];
    float4 o;
    o.x = fmaxf(fmaf(dn, acc.x, __ldg(&b1[lane * 4 + 0])), 0.f);
    o.y = fmaxf(fmaf(dn, acc.y, __ldg(&b1[lane * 4 + 1])), 0.f);
    o.z = fmaxf(fmaf(dn, acc.z, __ldg(&b1[lane * 4 + 2])), 0.f);
    o.w = fmaxf(fmaf(dn, acc.w, __ldg(&b1[lane * 4 + 3])), 0.f);
    ((float4*)g_h1)[node * 32 + lane] = o;
}

// ---------------------------------------------------------------- GEMM2 (FFMA2)
// g2[i][j] = dinv[i] * sum_k h1[i][k] * W2[k][j]
// 256 threads, 64-row tile, 64 cols. Thread (c=tid&15, r=tid>>4) does
// cols 4c..4c+3 (2 packed pairs) for rows r, r+16, r+32, r+48.
__global__ void __launch_bounds__(256) k_gemm2(const float* __restrict__ W2) {
    extern __shared__ float sm[];
    float* sW = sm;             // 128*64
    float* sX = sm + 128 * 64;  // 64*128
    int tid = threadIdx.x;
    int row0 = blockIdx.x * 64;

    for (int i = tid; i < 128 * 64 / 4; i += 256)
        ((float4*)sW)[i] = ((const float4*)W2)[i];
    for (int i = tid; i < 64 * 128 / 4; i += 256) {
        int r = i >> 5;
        int gr = row0 + r;
        ((float4*)sX)[i] = (gr < NN) ? ((const float4*)g_h1)[gr * 32 + (i & 31)]
                                     : make_float4(0.f, 0.f, 0.f, 0.f);
    }
    __syncthreads();

    int c = tid & 15;
    int r = tid >> 4;
    unsigned long long acc[4][2];
#pragma unroll
    for (int i = 0; i < 4; i++) { acc[i][0] = pk2(0.f, 0.f); acc[i][1] = pk2(0.f, 0.f); }

#pragma unroll 4
    for (int k = 0; k < 128; k++) {
        float4 w = ((const float4*)sW)[k * 16 + c];
        unsigned long long w01 = pk2(w.x, w.y);
        unsigned long long w23 = pk2(w.z, w.w);
#pragma unroll
        for (int i = 0; i < 4; i++) {
            float xv = sX[(r + 16 * i) * 128 + k];
            unsigned long long xx = pk2(xv, xv);
            fma2(acc[i][0], xx, w01);
            fma2(acc[i][1], xx, w23);
        }
    }

#pragma unroll
    for (int i = 0; i < 4; i++) {
        int gr = row0 + r + 16 * i;
        if (gr < NN) {
            float s = g_dinv[gr];
            float2 p0 = upk2(acc[i][0]);
            float2 p1 = upk2(acc[i][1]);
            ((float4*)g_g2)[gr * 16 + c] =
                make_float4(s * p0.x, s * p0.y, s * p1.x, s * p1.y);
        }
    }
}

// ---------------------------------------------------------------- aggregate2
__global__ void __launch_bounds__(256) k_agg2(const float* __restrict__ b2,
                                              float* __restrict__ out) {
    int t = blockIdx.x * 256 + threadIdx.x;
    int node = t >> 4;
    int l = t & 15;
    if (node >= NN) return;
    int beg = g_rowstart[node];
    int end = g_rowstart[node + 1];
    float4 acc = ((const float4*)g_g2)[node * 16 + l];
    for (int i = beg; i < end; i++) {
        int s = g_csr[i];
        float4 v = ((const float4*)g_g2)[s * 16 + l];
        acc.x += v.x; acc.y += v.y; acc.z += v.z; acc.w += v.w;
    }
    float dn = g_dinv[node];
    float4 o;
    o.x = fmaf(dn, acc.x, __ldg(&b2[l * 4 + 0]));
    o.y = fmaf(dn, acc.y, __ldg(&b2[l * 4 + 1]));
    o.z = fmaf(dn, acc.z, __ldg(&b2[l * 4 + 2]));
    o.w = fmaf(dn, acc.w, __ldg(&b2[l * 4 + 3]));
    ((float4*)out)[node * 16 + l] = o;
}

// ----------------------------------------------------------------
extern "C" void kernel_launch(void* const* d_in, const int* in_sizes, int n_in,
                              void* d_out, int out_size) {
    const float* x  = (const float*)d_in[0];
    const int*   ei = (const int*)d_in[1];
    const float* W1 = (const float*)d_in[2];
    const float* b1 = (const float*)d_in[3];
    const float* W2 = (const float*)d_in[4];
    const float* b2 = (const float*)d_in[5];
    float* out = (float*)d_out;

    const int smem1 = (128 * 128 + 64 * 128) * 4;  // 96 KB
    const int smem2 = (128 * 64 + 64 * 128) * 4;   // 64 KB
    cudaFuncSetAttribute(k_gemm1, cudaFuncAttributeMaxDynamicSharedMemorySize, smem1);
    cudaFuncSetAttribute(k_gemm2, cudaFuncAttributeMaxDynamicSharedMemorySize, smem2);

    k_detect<<<1, 256>>>(ei);
    k_zero <<<(NN + 255) / 256, 256>>>();
    k_count<<<(NE + 255) / 256, 256>>>(ei);
    k_scan_local <<<NBLK, SCAN_B>>>();
    k_scan_blocks<<<1, 128>>>();
    k_scan_add   <<<NBLK, SCAN_B>>>();
    k_dinv <<<(NN + 255) / 256, 256>>>();
    k_fill <<<(NE + 255) / 256, 256>>>(ei);

    k_gemm1<<<(NN + 63) / 64, 256, smem1>>>(x, W1);
    k_agg1 <<<(NN * 32 + 255) / 256, 256>>>(b1);

    k_gemm2<<<(NN + 63) / 64, 256, smem2>>>(W2);
    k_agg2 <<<(NN * 16 + 255) / 256, 256>>>(b2, out);
}

// round 10
// speedup vs baseline: 1.3659x; 1.0233x over previous
#include <cuda_runtime.h>
#include <cstdint>

#define NN 100000
#define NE 600000
#define SCAN_B 1024
#define NBLK ((NN + SCAN_B - 1) / SCAN_B)   // 98
typedef unsigned long long ULL;

// Scratch (device globals: no allocation allowed anywhere).
__device__ __align__(16) int   g_deg[NN];
__device__ __align__(16) int   g_cnt[NN];
__device__ __align__(16) int   g_rowstart[NN + 1];
__device__ __align__(16) int   g_blocksum[NBLK];
__device__ __align__(16) int   g_csr[NE];
__device__ __align__(16) float g_dinv[NN];
__device__ __align__(16) float g_W1p[128 * 128];  // pair-interleaved W1
__device__ __align__(16) float g_W2p[128 * 64];   // pair-interleaved W2
__device__ __align__(16) float g_g1[NN * 128];    // dinv * (x @ W1)
__device__ __align__(16) float g_h1[NN * 128];    // relu(dinv*agg + b1)
__device__ __align__(16) float g_g2[NN * 64];     // dinv * (h1 @ W2)
__device__ int g_is64;

__device__ __forceinline__ int edge_src(const int* ei, int e) {
    return g_is64 ? (int)((const long long*)ei)[e] : ei[e];
}
__device__ __forceinline__ int edge_dst(const int* ei, int e) {
    return g_is64 ? (int)((const long long*)ei)[NE + e] : ei[NE + e];
}

// ---- packed f32x2 helpers ----
__device__ __forceinline__ ULL pk2(float a, float b) {
    ULL r;
    asm("mov.b64 %0, {%1, %2};" : "=l"(r) : "f"(a), "f"(b));
    return r;
}
__device__ __forceinline__ void fma2(ULL& d, ULL a, ULL b) {
    asm("fma.rn.f32x2 %0, %1, %2, %0;" : "+l"(d) : "l"(a), "l"(b));
}
__device__ __forceinline__ float2 upk2(ULL v) {
    float2 f;
    asm("mov.b64 {%0, %1}, %2;" : "=f"(f.x), "=f"(f.y) : "l"(v));
    return f;
}

// ---------------------------------------------------------------- zero + detect
__global__ void k_zero_detect(const int* __restrict__ ei) {
    int i = blockIdx.x * blockDim.x + threadIdx.x;
    if (i < NN) { g_deg[i] = 0; g_cnt[i] = 0; }
    if (blockIdx.x == 0) {
        __shared__ int flag;
        if (threadIdx.x == 0) flag = 0;
        __syncthreads();
        int any = 0;
        for (int j = threadIdx.x; j < 4096; j += 256)
            if (ei[2 * j + 1] != 0) any = 1;
        if (any) flag = 1;
        __syncthreads();
        if (threadIdx.x == 0) g_is64 = flag ? 0 : 1;
    }
}

// ---------------------------------------------------------------- W pair-pack
// g_W1p float4 idx (k2*64 + c2) = {W[2k2][2c2], W[2k2+1][2c2], W[2k2][2c2+1], W[2k2+1][2c2+1]}
__global__ void k_packW1(const float* __restrict__ W) {
    int i = blockIdx.x * blockDim.x + threadIdx.x;   // 64*64
    if (i >= 64 * 64) return;
    int k2 = i >> 6, c2 = i & 63;
    float4 v;
    v.x = W[(2 * k2) * 128 + 2 * c2];
    v.y = W[(2 * k2 + 1) * 128 + 2 * c2];
    v.z = W[(2 * k2) * 128 + 2 * c2 + 1];
    v.w = W[(2 * k2 + 1) * 128 + 2 * c2 + 1];
    ((float4*)g_W1p)[i] = v;
}

__global__ void k_packW2(const float* __restrict__ W) {
    int i = blockIdx.x * blockDim.x + threadIdx.x;   // 64*32
    if (i >= 64 * 32) return;
    int k2 = i >> 5, c2 = i & 31;
    float4 v;
    v.x = W[(2 * k2) * 64 + 2 * c2];
    v.y = W[(2 * k2 + 1) * 64 + 2 * c2];
    v.z = W[(2 * k2) * 64 + 2 * c2 + 1];
    v.w = W[(2 * k2 + 1) * 64 + 2 * c2 + 1];
    ((float4*)g_W2p)[i] = v;
}

// ---------------------------------------------------------------- count
__global__ void k_count(const int* __restrict__ ei) {
    int e = blockIdx.x * blockDim.x + threadIdx.x;
    if (e < NE) {
        int d = edge_dst(ei, e);
        if (d >= 0 && d < NN) atomicAdd(&g_deg[d], 1);
    }
}

// ---------------------------------------------------------------- scan (+dinv fused)
__global__ void __launch_bounds__(SCAN_B) k_scan_local() {
    __shared__ int wsum[32];
    int tid = threadIdx.x, lane = tid & 31, wid = tid >> 5;
    int gid = blockIdx.x * SCAN_B + tid;
    int v = (gid < NN) ? g_deg[gid] : 0;
    if (gid < NN) g_dinv[gid] = rsqrtf((float)(v + 1));
    int s = v;
#pragma unroll
    for (int o = 1; o < 32; o <<= 1) {
        int t = __shfl_up_sync(0xffffffffu, s, o);
        if (lane >= o) s += t;
    }
    if (lane == 31) wsum[wid] = s;
    __syncthreads();
    if (wid == 0) {
        int ws = wsum[lane];
#pragma unroll
        for (int o = 1; o < 32; o <<= 1) {
            int t = __shfl_up_sync(0xffffffffu, ws, o);
            if (lane >= o) ws += t;
        }
        wsum[lane] = ws;
    }
    __syncthreads();
    int base = (wid > 0) ? wsum[wid - 1] : 0;
    if (gid < NN) g_rowstart[gid] = base + s - v;      // exclusive
    if (tid == SCAN_B - 1) g_blocksum[blockIdx.x] = base + s;
}

__global__ void k_scan_blocks() {
    __shared__ int s[NBLK];
    int tid = threadIdx.x;
    if (tid < NBLK) s[tid] = g_blocksum[tid];
    __syncthreads();
    if (tid == 0) {
        int run = 0;
        for (int i = 0; i < NBLK; i++) { int t = s[i]; s[i] = run; run += t; }
        g_rowstart[NN] = run;
    }
    __syncthreads();
    if (tid < NBLK) g_blocksum[tid] = s[tid];
}

__global__ void __launch_bounds__(SCAN_B) k_scan_add() {
    int gid = blockIdx.x * SCAN_B + threadIdx.x;
    if (gid < NN) g_rowstart[gid] += g_blocksum[blockIdx.x];
}

// ---------------------------------------------------------------- CSR fill
__global__ void k_fill(const int* __restrict__ ei) {
    int e = blockIdx.x * blockDim.x + threadIdx.x;
    if (e >= NE) return;
    int s = edge_src(ei, e);
    int d = edge_dst(ei, e);
    if (s < 0 || s >= NN || d < 0 || d >= NN) return;
    int pos = g_rowstart[d] + atomicAdd(&g_cnt[d], 1);
    g_csr[pos] = s;
}

// ---------------------------------------------------------------- GEMM1 (FFMA2, k-pair)
// g1 = dinv ⊙ (x @ W1). 64-row tile. Thread (c=tid&31, r=tid>>5):
// cols {2c,2c+1,64+2c,65+2c}, rows r,r+8,...,r+56. Zero pack movs.
__global__ void __launch_bounds__(256) k_gemm1(const float* __restrict__ x) {
    extern __shared__ float sm[];
    float* sWp = sm;              // 128*128 (pair-interleaved)
    float* sX  = sm + 128 * 128;  // 64*128
    int tid = threadIdx.x;
    int row0 = blockIdx.x * 64;

    for (int i = tid; i < 128 * 128 / 4; i += 256)
        ((float4*)sWp)[i] = ((const float4*)g_W1p)[i];
    for (int i = tid; i < 64 * 128 / 4; i += 256) {
        int r = i >> 5, gr = row0 + r;
        ((float4*)sX)[i] = (gr < NN) ? ((const float4*)x)[gr * 32 + (i & 31)]
                                     : make_float4(0.f, 0.f, 0.f, 0.f);
    }
    __syncthreads();

    int c = tid & 31;
    int r = tid >> 5;
    ULL acc[8][4];
#pragma unroll
    for (int i = 0; i < 8; i++)
#pragma unroll
        for (int j = 0; j < 4; j++) acc[i][j] = pk2(0.f, 0.f);

#pragma unroll 4
    for (int k2 = 0; k2 < 64; k2++) {
        ulonglong2 wA = ((const ulonglong2*)sWp)[k2 * 64 + c];       // cols 2c,2c+1
        ulonglong2 wB = ((const ulonglong2*)sWp)[k2 * 64 + 32 + c];  // cols 64+2c,65+2c
#pragma unroll
        for (int i = 0; i < 8; i++) {
            ULL xp = ((const ULL*)sX)[(r + 8 * i) * 64 + k2];        // broadcast
            fma2(acc[i][0], xp, wA.x);
            fma2(acc[i][1], xp, wA.y);
            fma2(acc[i][2], xp, wB.x);
            fma2(acc[i][3], xp, wB.y);
        }
    }

#pragma unroll
    for (int i = 0; i < 8; i++) {
        int gr = row0 + r + 8 * i;
        if (gr < NN) {
            float s = g_dinv[gr];
            float2 p0 = upk2(acc[i][0]), p1 = upk2(acc[i][1]);
            float2 p2 = upk2(acc[i][2]), p3 = upk2(acc[i][3]);
            ((float2*)g_g1)[gr * 64 + c]      = make_float2(s * (p0.x + p0.y), s * (p1.x + p1.y));
            ((float2*)g_g1)[gr * 64 + 32 + c] = make_float2(s * (p2.x + p2.y), s * (p3.x + p3.y));
        }
    }
}

// ---------------------------------------------------------------- aggregate1
__global__ void __launch_bounds__(256) k_agg1(const float* __restrict__ b1) {
    int node = (blockIdx.x * 256 + threadIdx.x) >> 5;
    int lane = threadIdx.x & 31;
    if (node >= NN) return;
    int beg = g_rowstart[node];
    int end = g_rowstart[node + 1];
    float4 acc = ((const float4*)g_g1)[node * 32 + lane];
    int i = beg;
    for (; i + 1 < end; i += 2) {
        int s0 = g_csr[i], s1 = g_csr[i + 1];
        float4 v0 = ((const float4*)g_g1)[s0 * 32 + lane];
        float4 v1 = ((const float4*)g_g1)[s1 * 32 + lane];
        acc.x += v0.x + v1.x; acc.y += v0.y + v1.y;
        acc.z += v0.z + v1.z; acc.w += v0.w + v1.w;
    }
    if (i < end) {
        float4 v = ((const float4*)g_g1)[g_csr[i] * 32 + lane];
        acc.x += v.x; acc.y += v.y; acc.z += v.z; acc.w += v.w;
    }
    float dn = g_dinv[node];
    float4 o;
    o.x = fmaxf(fmaf(dn, acc.x, __ldg(&b1[lane * 4 + 0])), 0.f);
    o.y = fmaxf(fmaf(dn, acc.y, __ldg(&b1[lane * 4 + 1])), 0.f);
    o.z = fmaxf(fmaf(dn, acc.z, __ldg(&b1[lane * 4 + 2])), 0.f);
    o.w = fmaxf(fmaf(dn, acc.w, __ldg(&b1[lane * 4 + 3])), 0.f);
    ((float4*)g_h1)[node * 32 + lane] = o;
}

// ---------------------------------------------------------------- GEMM2 (FFMA2, k-pair)
// g2 = dinv ⊙ (h1 @ W2). Thread (c=tid&15, r=tid>>4):
// cols {2c,2c+1,32+2c,33+2c}, rows r,r+16,r+32,r+48.
__global__ void __launch_bounds__(256) k_gemm2() {
    extern __shared__ float sm[];
    float* sWp = sm;             // 128*64 (pair-interleaved)
    float* sX  = sm + 128 * 64;  // 64*128
    int tid = threadIdx.x;
    int row0 = blockIdx.x * 64;

    for (int i = tid; i < 128 * 64 / 4; i += 256)
        ((float4*)sWp)[i] = ((const float4*)g_W2p)[i];
    for (int i = tid; i < 64 * 128 / 4; i += 256) {
        int r = i >> 5, gr = row0 + r;
        ((float4*)sX)[i] = (gr < NN) ? ((const float4*)g_h1)[gr * 32 + (i & 31)]
                                     : make_float4(0.f, 0.f, 0.f, 0.f);
    }
    __syncthreads();

    int c = tid & 15;
    int r = tid >> 4;
    ULL acc[4][4];
#pragma unroll
    for (int i = 0; i < 4; i++)
#pragma unroll
        for (int j = 0; j < 4; j++) acc[i][j] = pk2(0.f, 0.f);

#pragma unroll 4
    for (int k2 = 0; k2 < 64; k2++) {
        ulonglong2 wA = ((const ulonglong2*)sWp)[k2 * 32 + c];       // cols 2c,2c+1
        ulonglong2 wB = ((const ulonglong2*)sWp)[k2 * 32 + 16 + c];  // cols 32+2c,33+2c
#pragma unroll
        for (int i = 0; i < 4; i++) {
            ULL xp = ((const ULL*)sX)[(r + 16 * i) * 64 + k2];
            fma2(acc[i][0], xp, wA.x);
            fma2(acc[i][1], xp, wA.y);
            fma2(acc[i][2], xp, wB.x);
            fma2(acc[i][3], xp, wB.y);
        }
    }

#pragma unroll
    for (int i = 0; i < 4; i++) {
        int gr = row0 + r + 16 * i;
        if (gr < NN) {
            float s = g_dinv[gr];
            float2 p0 = upk2(acc[i][0]), p1 = upk2(acc[i][1]);
            float2 p2 = upk2(acc[i][2]), p3 = upk2(acc[i][3]);
            ((float2*)g_g2)[gr * 32 + c]      = make_float2(s * (p0.x + p0.y), s * (p1.x + p1.y));
            ((float2*)g_g2)[gr * 32 + 16 + c] = make_float2(s * (p2.x + p2.y), s * (p3.x + p3.y));
        }
    }
}

// ---------------------------------------------------------------- aggregate2
__global__ void __launch_bounds__(256) k_agg2(const float* __restrict__ b2,
                                              float* __restrict__ out) {
    int t = blockIdx.x * 256 + threadIdx.x;
    int node = t >> 4;
    int l = t & 15;
    if (node >= NN) return;
    int beg = g_rowstart[node];
    int end = g_rowstart[node + 1];
    float4 acc = ((const float4*)g_g2)[node * 16 + l];
    int i = beg;
    for (; i + 1 < end; i += 2) {
        int s0 = g_csr[i], s1 = g_csr[i + 1];
        float4 v0 = ((const float4*)g_g2)[s0 * 16 + l];
        float4 v1 = ((const float4*)g_g2)[s1 * 16 + l];
        acc.x += v0.x + v1.x; acc.y += v0.y + v1.y;
        acc.z += v0.z + v1.z; acc.w += v0.w + v1.w;
    }
    if (i < end) {
        float4 v = ((const float4*)g_g2)[g_csr[i] * 16 + l];
        acc.x += v.x; acc.y += v.y; acc.z += v.z; acc.w += v.w;
    }
    float dn = g_dinv[node];
    float4 o;
    o.x = fmaf(dn, acc.x, __ldg(&b2[l * 4 + 0]));
    o.y = fmaf(dn, acc.y, __ldg(&b2[l * 4 + 1]));
    o.z = fmaf(dn, acc.z, __ldg(&b2[l * 4 + 2]));
    o.w = fmaf(dn, acc.w, __ldg(&b2[l * 4 + 3]));
    ((float4*)out)[node * 16 + l] = o;
}

// ----------------------------------------------------------------
extern "C" void kernel_launch(void* const* d_in, const int* in_sizes, int n_in,
                              void* d_out, int out_size) {
    const float* x  = (const float*)d_in[0];
    const int*   ei = (const int*)d_in[1];
    const float* W1 = (const float*)d_in[2];
    const float* b1 = (const float*)d_in[3];
    const float* W2 = (const float*)d_in[4];
    const float* b2 = (const float*)d_in[5];
    float* out = (float*)d_out;

    const int smem1 = (128 * 128 + 64 * 128) * 4;  // 96 KB
    const int smem2 = (128 * 64 + 64 * 128) * 4;   // 64 KB
    cudaFuncSetAttribute(k_gemm1, cudaFuncAttributeMaxDynamicSharedMemorySize, smem1);
    cudaFuncSetAttribute(k_gemm2, cudaFuncAttributeMaxDynamicSharedMemorySize, smem2);

    k_zero_detect<<<(NN + 255) / 256, 256>>>(ei);
    k_packW1<<<(64 * 64 + 255) / 256, 256>>>(W1);
    k_packW2<<<(64 * 32 + 255) / 256, 256>>>(W2);
    k_count<<<(NE + 255) / 256, 256>>>(ei);
    k_scan_local <<<NBLK, SCAN_B>>>();
    k_scan_blocks<<<1, 128>>>();
    k_scan_add   <<<NBLK, SCAN_B>>>();
    k_fill <<<(NE + 255) / 256, 256>>>(ei);

    k_gemm1<<<(NN + 63) / 64, 256, smem1>>>(x);
    k_agg1 <<<(NN * 32 + 255) / 256, 256>>>(b1);

    k_gemm2<<<(NN + 63) / 64, 256, smem2>>>();
    k_agg2 <<<(NN * 16 + 255) / 256, 256>>>(b2, out);
}

// round 11
// speedup vs baseline: 1.4522x; 1.0632x over previous
#include <cuda_runtime.h>
#include <cstdint>

#define NN 100000
#define NE 600000
#define SCAN_B 1024
#define NBLK ((NN + SCAN_B - 1) / SCAN_B)   // 98
typedef unsigned long long ULL;

// Scratch (device globals: no allocation allowed anywhere).
__device__ __align__(16) int   g_deg[NN];
__device__ __align__(16) int   g_cnt[NN];
__device__ __align__(16) int   g_rowstart[NN + 1];
__device__ __align__(16) int   g_blocksum[NBLK];
__device__ __align__(16) int   g_csr[NE];
__device__ __align__(16) float g_dinv[NN];
__device__ __align__(16) float g_W1p[128 * 128];  // pair-interleaved W1
__device__ __align__(16) float g_W2p[128 * 64];   // pair-interleaved W2
__device__ __align__(16) float g_g1[NN * 128];    // dinv * (x @ W1)
__device__ __align__(16) float g_h1[NN * 128];    // relu(dinv*agg + b1)
__device__ __align__(16) float g_g2[NN * 64];     // dinv * (h1 @ W2)
__device__ int g_is64;

__device__ __forceinline__ int edge_src(const int* ei, int e) {
    return g_is64 ? (int)((const long long*)ei)[e] : ei[e];
}
__device__ __forceinline__ int edge_dst(const int* ei, int e) {
    return g_is64 ? (int)((const long long*)ei)[NE + e] : ei[NE + e];
}

// ---- packed f32x2 helpers ----
__device__ __forceinline__ ULL pk2(float a, float b) {
    ULL r;
    asm("mov.b64 %0, {%1, %2};" : "=l"(r) : "f"(a), "f"(b));
    return r;
}
__device__ __forceinline__ void fma2(ULL& d, ULL a, ULL b) {
    asm("fma.rn.f32x2 %0, %1, %2, %0;" : "+l"(d) : "l"(a), "l"(b));
}
__device__ __forceinline__ float2 upk2(ULL v) {
    float2 f;
    asm("mov.b64 {%0, %1}, %2;" : "=f"(f.x), "=f"(f.y) : "l"(v));
    return f;
}

// ---------------------------------------------------------------- pre
// Fused: zero deg/cnt (all blocks), edge-layout detect (block 0),
// W1 pair-pack (blocks 1..16), W2 pair-pack (blocks 17..24).
__global__ void __launch_bounds__(256) k_pre(const int* __restrict__ ei,
                                             const float* __restrict__ W1,
                                             const float* __restrict__ W2) {
    int bid = blockIdx.x;
    int i = bid * 256 + threadIdx.x;
    if (i < NN) { g_deg[i] = 0; g_cnt[i] = 0; }

    if (bid == 0) {
        __shared__ int flag;
        if (threadIdx.x == 0) flag = 0;
        __syncthreads();
        int any = 0;
        for (int j = threadIdx.x; j < 4096; j += 256)
            if (ei[2 * j + 1] != 0) any = 1;
        if (any) flag = 1;
        __syncthreads();
        if (threadIdx.x == 0) g_is64 = flag ? 0 : 1;
    } else if (bid <= 16) {
        // packW1: 64*64 float4 entries, 16 blocks x 256 threads
        int p = (bid - 1) * 256 + threadIdx.x;      // < 4096
        int k2 = p >> 6, c2 = p & 63;
        float4 v;
        v.x = W1[(2 * k2) * 128 + 2 * c2];
        v.y = W1[(2 * k2 + 1) * 128 + 2 * c2];
        v.z = W1[(2 * k2) * 128 + 2 * c2 + 1];
        v.w = W1[(2 * k2 + 1) * 128 + 2 * c2 + 1];
        ((float4*)g_W1p)[p] = v;
    } else if (bid <= 24) {
        // packW2: 64*32 float4 entries, 8 blocks x 256 threads
        int p = (bid - 17) * 256 + threadIdx.x;     // < 2048
        int k2 = p >> 5, c2 = p & 31;
        float4 v;
        v.x = W2[(2 * k2) * 64 + 2 * c2];
        v.y = W2[(2 * k2 + 1) * 64 + 2 * c2];
        v.z = W2[(2 * k2) * 64 + 2 * c2 + 1];
        v.w = W2[(2 * k2 + 1) * 64 + 2 * c2 + 1];
        ((float4*)g_W2p)[p] = v;
    }
}

// ---------------------------------------------------------------- count
__global__ void k_count(const int* __restrict__ ei) {
    int e = blockIdx.x * blockDim.x + threadIdx.x;
    if (e < NE) {
        int d = edge_dst(ei, e);
        if (d >= 0 && d < NN) atomicAdd(&g_deg[d], 1);
    }
}

// ---------------------------------------------------------------- scan (+dinv fused)
__global__ void __launch_bounds__(SCAN_B) k_scan_local() {
    __shared__ int wsum[32];
    int tid = threadIdx.x, lane = tid & 31, wid = tid >> 5;
    int gid = blockIdx.x * SCAN_B + tid;
    int v = (gid < NN) ? g_deg[gid] : 0;
    if (gid < NN) g_dinv[gid] = rsqrtf((float)(v + 1));
    int s = v;
#pragma unroll
    for (int o = 1; o < 32; o <<= 1) {
        int t = __shfl_up_sync(0xffffffffu, s, o);
        if (lane >= o) s += t;
    }
    if (lane == 31) wsum[wid] = s;
    __syncthreads();
    if (wid == 0) {
        int ws = wsum[lane];
#pragma unroll
        for (int o = 1; o < 32; o <<= 1) {
            int t = __shfl_up_sync(0xffffffffu, ws, o);
            if (lane >= o) ws += t;
        }
        wsum[lane] = ws;
    }
    __syncthreads();
    int base = (wid > 0) ? wsum[wid - 1] : 0;
    if (gid < NN) g_rowstart[gid] = base + s - v;      // exclusive
    if (tid == SCAN_B - 1) g_blocksum[blockIdx.x] = base + s;
}

__global__ void k_scan_blocks() {
    __shared__ int s[NBLK];
    int tid = threadIdx.x;
    if (tid < NBLK) s[tid] = g_blocksum[tid];
    __syncthreads();
    if (tid == 0) {
        int run = 0;
        for (int i = 0; i < NBLK; i++) { int t = s[i]; s[i] = run; run += t; }
        g_rowstart[NN] = run;
    }
    __syncthreads();
    if (tid < NBLK) g_blocksum[tid] = s[tid];
}

__global__ void __launch_bounds__(SCAN_B) k_scan_add() {
    int gid = blockIdx.x * SCAN_B + threadIdx.x;
    if (gid < NN) g_rowstart[gid] += g_blocksum[blockIdx.x];
}

// ---------------------------------------------------------------- CSR fill
__global__ void k_fill(const int* __restrict__ ei) {
    int e = blockIdx.x * blockDim.x + threadIdx.x;
    if (e >= NE) return;
    int s = edge_src(ei, e);
    int d = edge_dst(ei, e);
    if (s < 0 || s >= NN || d < 0 || d >= NN) return;
    int pos = g_rowstart[d] + atomicAdd(&g_cnt[d], 1);
    g_csr[pos] = s;
}

// ---------------------------------------------------------------- GEMM1 (FFMA2, k-pair)
__global__ void __launch_bounds__(256) k_gemm1(const float* __restrict__ x) {
    extern __shared__ float sm[];
    float* sWp = sm;              // 128*128 (pair-interleaved)
    float* sX  = sm + 128 * 128;  // 64*128
    int tid = threadIdx.x;
    int row0 = blockIdx.x * 64;

    for (int i = tid; i < 128 * 128 / 4; i += 256)
        ((float4*)sWp)[i] = ((const float4*)g_W1p)[i];
    for (int i = tid; i < 64 * 128 / 4; i += 256) {
        int r = i >> 5, gr = row0 + r;
        ((float4*)sX)[i] = (gr < NN) ? ((const float4*)x)[gr * 32 + (i & 31)]
                                     : make_float4(0.f, 0.f, 0.f, 0.f);
    }
    __syncthreads();

    int c = tid & 31;
    int r = tid >> 5;
    ULL acc[8][4];
#pragma unroll
    for (int i = 0; i < 8; i++)
#pragma unroll
        for (int j = 0; j < 4; j++) acc[i][j] = pk2(0.f, 0.f);

#pragma unroll 4
    for (int k2 = 0; k2 < 64; k2++) {
        ulonglong2 wA = ((const ulonglong2*)sWp)[k2 * 64 + c];
        ulonglong2 wB = ((const ulonglong2*)sWp)[k2 * 64 + 32 + c];
#pragma unroll
        for (int i = 0; i < 8; i++) {
            ULL xp = ((const ULL*)sX)[(r + 8 * i) * 64 + k2];
            fma2(acc[i][0], xp, wA.x);
            fma2(acc[i][1], xp, wA.y);
            fma2(acc[i][2], xp, wB.x);
            fma2(acc[i][3], xp, wB.y);
        }
    }

#pragma unroll
    for (int i = 0; i < 8; i++) {
        int gr = row0 + r + 8 * i;
        if (gr < NN) {
            float s = g_dinv[gr];
            float2 p0 = upk2(acc[i][0]), p1 = upk2(acc[i][1]);
            float2 p2 = upk2(acc[i][2]), p3 = upk2(acc[i][3]);
            ((float2*)g_g1)[gr * 64 + c]      = make_float2(s * (p0.x + p0.y), s * (p1.x + p1.y));
            ((float2*)g_g1)[gr * 64 + 32 + c] = make_float2(s * (p2.x + p2.y), s * (p3.x + p3.y));
        }
    }
}

// NOTE: g_g1 is written with dinv already applied, but k_gemm1 may run BEFORE
// k_scan_local writes g_dinv (fork). So dinv must NOT be read in gemm1.
// Fix: gemm1 writes raw x@W1; aggregate applies dinv[src] during gather.

// ---------------------------------------------------------------- GEMM1 (no dinv)
__global__ void __launch_bounds__(256) k_gemm1_raw(const float* __restrict__ x) {
    extern __shared__ float sm[];
    float* sWp = sm;
    float* sX  = sm + 128 * 128;
    int tid = threadIdx.x;
    int row0 = blockIdx.x * 64;

    for (int i = tid; i < 128 * 128 / 4; i += 256)
        ((float4*)sWp)[i] = ((const float4*)g_W1p)[i];
    for (int i = tid; i < 64 * 128 / 4; i += 256) {
        int r = i >> 5, gr = row0 + r;
        ((float4*)sX)[i] = (gr < NN) ? ((const float4*)x)[gr * 32 + (i & 31)]
                                     : make_float4(0.f, 0.f, 0.f, 0.f);
    }
    __syncthreads();

    int c = tid & 31;
    int r = tid >> 5;
    ULL acc[8][4];
#pragma unroll
    for (int i = 0; i < 8; i++)
#pragma unroll
        for (int j = 0; j < 4; j++) acc[i][j] = pk2(0.f, 0.f);

#pragma unroll 4
    for (int k2 = 0; k2 < 64; k2++) {
        ulonglong2 wA = ((const ulonglong2*)sWp)[k2 * 64 + c];
        ulonglong2 wB = ((const ulonglong2*)sWp)[k2 * 64 + 32 + c];
#pragma unroll
        for (int i = 0; i < 8; i++) {
            ULL xp = ((const ULL*)sX)[(r + 8 * i) * 64 + k2];
            fma2(acc[i][0], xp, wA.x);
            fma2(acc[i][1], xp, wA.y);
            fma2(acc[i][2], xp, wB.x);
            fma2(acc[i][3], xp, wB.y);
        }
    }

#pragma unroll
    for (int i = 0; i < 8; i++) {
        int gr = row0 + r + 8 * i;
        if (gr < NN) {
            float2 p0 = upk2(acc[i][0]), p1 = upk2(acc[i][1]);
            float2 p2 = upk2(acc[i][2]), p3 = upk2(acc[i][3]);
            ((float2*)g_g1)[gr * 64 + c]      = make_float2(p0.x + p0.y, p1.x + p1.y);
            ((float2*)g_g1)[gr * 64 + 32 + c] = make_float2(p2.x + p2.y, p3.x + p3.y);
        }
    }
}

// ---------------------------------------------------------------- aggregate1
// h1[n] = relu(dinv[n]*(dinv[n]*g1[n] + sum_s dinv[s]*g1[s]) + b1); 4x unrolled.
__global__ void __launch_bounds__(256) k_agg1(const float* __restrict__ b1) {
    int node = (blockIdx.x * 256 + threadIdx.x) >> 5;
    int lane = threadIdx.x & 31;
    if (node >= NN) return;
    int beg = g_rowstart[node];
    int end = g_rowstart[node + 1];
    float dn = g_dinv[node];
    float4 sv = ((const float4*)g_g1)[node * 32 + lane];
    float4 acc = make_float4(dn * sv.x, dn * sv.y, dn * sv.z, dn * sv.w);
    int i = beg;
    for (; i + 3 < end; i += 4) {
        int s0 = g_csr[i], s1 = g_csr[i + 1], s2 = g_csr[i + 2], s3 = g_csr[i + 3];
        float d0 = g_dinv[s0], d1 = g_dinv[s1], d2 = g_dinv[s2], d3 = g_dinv[s3];
        float4 v0 = ((const float4*)g_g1)[s0 * 32 + lane];
        float4 v1 = ((const float4*)g_g1)[s1 * 32 + lane];
        float4 v2 = ((const float4*)g_g1)[s2 * 32 + lane];
        float4 v3 = ((const float4*)g_g1)[s3 * 32 + lane];
        acc.x += d0 * v0.x + d1 * v1.x + d2 * v2.x + d3 * v3.x;
        acc.y += d0 * v0.y + d1 * v1.y + d2 * v2.y + d3 * v3.y;
        acc.z += d0 * v0.z + d1 * v1.z + d2 * v2.z + d3 * v3.z;
        acc.w += d0 * v0.w + d1 * v1.w + d2 * v2.w + d3 * v3.w;
    }
    for (; i < end; i++) {
        int s = g_csr[i];
        float d = g_dinv[s];
        float4 v = ((const float4*)g_g1)[s * 32 + lane];
        acc.x += d * v.x; acc.y += d * v.y; acc.z += d * v.z; acc.w += d * v.w;
    }
    float4 o;
    o.x = fmaxf(fmaf(dn, acc.x, __ldg(&b1[lane * 4 + 0])), 0.f);
    o.y = fmaxf(fmaf(dn, acc.y, __ldg(&b1[lane * 4 + 1])), 0.f);
    o.z = fmaxf(fmaf(dn, acc.z, __ldg(&b1[lane * 4 + 2])), 0.f);
    o.w = fmaxf(fmaf(dn, acc.w, __ldg(&b1[lane * 4 + 3])), 0.f);
    ((float4*)g_h1)[node * 32 + lane] = o;
}

// ---------------------------------------------------------------- GEMM2 (FFMA2, k-pair)
__global__ void __launch_bounds__(256) k_gemm2() {
    extern __shared__ float sm[];
    float* sWp = sm;             // 128*64 (pair-interleaved)
    float* sX  = sm + 128 * 64;  // 64*128
    int tid = threadIdx.x;
    int row0 = blockIdx.x * 64;

    for (int i = tid; i < 128 * 64 / 4; i += 256)
        ((float4*)sWp)[i] = ((const float4*)g_W2p)[i];
    for (int i = tid; i < 64 * 128 / 4; i += 256) {
        int r = i >> 5, gr = row0 + r;
        ((float4*)sX)[i] = (gr < NN) ? ((const float4*)g_h1)[gr * 32 + (i & 31)]
                                     : make_float4(0.f, 0.f, 0.f, 0.f);
    }
    __syncthreads();

    int c = tid & 15;
    int r = tid >> 4;
    ULL acc[4][4];
#pragma unroll
    for (int i = 0; i < 4; i++)
#pragma unroll
        for (int j = 0; j < 4; j++) acc[i][j] = pk2(0.f, 0.f);

#pragma unroll 4
    for (int k2 = 0; k2 < 64; k2++) {
        ulonglong2 wA = ((const ulonglong2*)sWp)[k2 * 32 + c];
        ulonglong2 wB = ((const ulonglong2*)sWp)[k2 * 32 + 16 + c];
#pragma unroll
        for (int i = 0; i < 4; i++) {
            ULL xp = ((const ULL*)sX)[(r + 16 * i) * 64 + k2];
            fma2(acc[i][0], xp, wA.x);
            fma2(acc[i][1], xp, wA.y);
            fma2(acc[i][2], xp, wB.x);
            fma2(acc[i][3], xp, wB.y);
        }
    }

#pragma unroll
    for (int i = 0; i < 4; i++) {
        int gr = row0 + r + 16 * i;
        if (gr < NN) {
            float s = g_dinv[gr];
            float2 p0 = upk2(acc[i][0]), p1 = upk2(acc[i][1]);
            float2 p2 = upk2(acc[i][2]), p3 = upk2(acc[i][3]);
            ((float2*)g_g2)[gr * 32 + c]      = make_float2(s * (p0.x + p0.y), s * (p1.x + p1.y));
            ((float2*)g_g2)[gr * 32 + 16 + c] = make_float2(s * (p2.x + p2.y), s * (p3.x + p3.y));
        }
    }
}

// ---------------------------------------------------------------- aggregate2
__global__ void __launch_bounds__(256) k_agg2(const float* __restrict__ b2,
                                              float* __restrict__ out) {
    int t = blockIdx.x * 256 + threadIdx.x;
    int node = t >> 4;
    int l = t & 15;
    if (node >= NN) return;
    int beg = g_rowstart[node];
    int end = g_rowstart[node + 1];
    float4 acc = ((const float4*)g_g2)[node * 16 + l];
    int i = beg;
    for (; i + 3 < end; i += 4) {
        int s0 = g_csr[i], s1 = g_csr[i + 1], s2 = g_csr[i + 2], s3 = g_csr[i + 3];
        float4 v0 = ((const float4*)g_g2)[s0 * 16 + l];
        float4 v1 = ((const float4*)g_g2)[s1 * 16 + l];
        float4 v2 = ((const float4*)g_g2)[s2 * 16 + l];
        float4 v3 = ((const float4*)g_g2)[s3 * 16 + l];
        acc.x += v0.x + v1.x + v2.x + v3.x;
        acc.y += v0.y + v1.y + v2.y + v3.y;
        acc.z += v0.z + v1.z + v2.z + v3.z;
        acc.w += v0.w + v1.w + v2.w + v3.w;
    }
    for (; i < end; i++) {
        float4 v = ((const float4*)g_g2)[g_csr[i] * 16 + l];
        acc.x += v.x; acc.y += v.y; acc.z += v.z; acc.w += v.w;
    }
    float dn = g_dinv[node];
    float4 o;
    o.x = fmaf(dn, acc.x, __ldg(&b2[l * 4 + 0]));
    o.y = fmaf(dn, acc.y, __ldg(&b2[l * 4 + 1]));
    o.z = fmaf(dn, acc.z, __ldg(&b2[l * 4 + 2]));
    o.w = fmaf(dn, acc.w, __ldg(&b2[l * 4 + 3]));
    ((float4*)out)[node * 16 + l] = o;
}

// ----------------------------------------------------------------
extern "C" void kernel_launch(void* const* d_in, const int* in_sizes, int n_in,
                              void* d_out, int out_size) {
    const float* x  = (const float*)d_in[0];
    const int*   ei = (const int*)d_in[1];
    const float* W1 = (const float*)d_in[2];
    const float* b1 = (const float*)d_in[3];
    const float* W2 = (const float*)d_in[4];
    const float* b2 = (const float*)d_in[5];
    float* out = (float*)d_out;

    const int smem1 = (128 * 128 + 64 * 128) * 4;  // 96 KB
    const int smem2 = (128 * 64 + 64 * 128) * 4;   // 64 KB
    cudaFuncSetAttribute(k_gemm1_raw, cudaFuncAttributeMaxDynamicSharedMemorySize, smem1);
    cudaFuncSetAttribute(k_gemm2,     cudaFuncAttributeMaxDynamicSharedMemorySize, smem2);

    // Fork a second stream so the edge-prep chain overlaps GEMM1.
    // (Host-side objects; created/destroyed per call, not graph nodes.)
    cudaStream_t s2;
    cudaEvent_t evA, evB;
    cudaStreamCreateWithFlags(&s2, cudaStreamNonBlocking);
    cudaEventCreateWithFlags(&evA, cudaEventDisableTiming);
    cudaEventCreateWithFlags(&evB, cudaEventDisableTiming);

    k_pre<<<(NN + 255) / 256, 256>>>(ei, W1, W2);

    cudaEventRecord(evA, 0);
    cudaStreamWaitEvent(s2, evA, 0);

    // prep chain on s2 (independent of GEMM1)
    k_count<<<(NE + 255) / 256, 256, 0, s2>>>(ei);
    k_scan_local <<<NBLK, SCAN_B, 0, s2>>>();
    k_scan_blocks<<<1, 128, 0, s2>>>();
    k_scan_add   <<<NBLK, SCAN_B, 0, s2>>>();
    k_fill<<<(NE + 255) / 256, 256, 0, s2>>>(ei);
    cudaEventRecord(evB, s2);

    // GEMM1 on main stream, concurrent with prep
    k_gemm1_raw<<<(NN + 63) / 64, 256, smem1>>>(x);

    cudaStreamWaitEvent(0, evB, 0);   // join

    k_agg1 <<<(NN * 32 + 255) / 256, 256>>>(b1);
    k_gemm2<<<(NN + 63) / 64, 256, smem2>>>();
    k_agg2 <<<(NN * 16 + 255) / 256, 256>>>(b2, out);

    cudaEventDestroy(evA);
    cudaEventDestroy(evB);
    cudaStreamDestroy(s2);
}

// round 13
// speedup vs baseline: 1.5135x; 1.0422x over previous
#include <cuda_runtime.h>
#include <cstdint>

#define NN 100000
#define NE 600000
#define SCAN_B 1024
#define NBLK ((NN + SCAN_B - 1) / SCAN_B)   // 98
typedef unsigned long long ULL;

// Scratch (device globals: no allocation allowed anywhere).
__device__ __align__(16) int   g_deg[NN];
__device__ __align__(16) int   g_cnt[NN];
__device__ __align__(16) int   g_rowstart[NN + 1];
__device__ __align__(16) int   g_blocksum[NBLK];
__device__ __align__(16) int   g_csr[NE];
__device__ __align__(16) float g_dinv[NN];
__device__ __align__(16) float g_W1p[128 * 128];  // pair-interleaved W1
__device__ __align__(16) float g_W2p[128 * 64];   // pair-interleaved W2
__device__ __align__(16) float g_g1[NN * 128];    // x @ W1 (raw, no dinv)
__device__ __align__(16) float g_g2[NN * 64];     // dinv * (h1 @ W2)
__device__ int g_is64;

__device__ __forceinline__ int edge_src(const int* ei, int e) {
    return g_is64 ? (int)((const long long*)ei)[e] : ei[e];
}
__device__ __forceinline__ int edge_dst(const int* ei, int e) {
    return g_is64 ? (int)((const long long*)ei)[NE + e] : ei[NE + e];
}

// ---- packed f32x2 helpers ----
__device__ __forceinline__ ULL pk2(float a, float b) {
    ULL r;
    asm("mov.b64 %0, {%1, %2};" : "=l"(r) : "f"(a), "f"(b));
    return r;
}
__device__ __forceinline__ void fma2(ULL& d, ULL a, ULL b) {
    asm("fma.rn.f32x2 %0, %1, %2, %0;" : "+l"(d) : "l"(a), "l"(b));
}
__device__ __forceinline__ float2 upk2(ULL v) {
    float2 f;
    asm("mov.b64 {%0, %1}, %2;" : "=f"(f.x), "=f"(f.y) : "l"(v));
    return f;
}

// ---------------------------------------------------------------- pre
// zero deg/cnt (all blocks); detect (block 0); W1 pack (1..16); W2 pack (17..24).
__global__ void __launch_bounds__(256) k_pre(const int* __restrict__ ei,
                                             const float* __restrict__ W1,
                                             const float* __restrict__ W2) {
    int bid = blockIdx.x;
    int i = bid * 256 + threadIdx.x;
    if (i < NN) { g_deg[i] = 0; g_cnt[i] = 0; }

    if (bid == 0) {
        __shared__ int flag;
        if (threadIdx.x == 0) flag = 0;
        __syncthreads();
        int any = 0;
        for (int j = threadIdx.x; j < 4096; j += 256)
            if (ei[2 * j + 1] != 0) any = 1;
        if (any) flag = 1;
        __syncthreads();
        if (threadIdx.x == 0) g_is64 = flag ? 0 : 1;
    } else if (bid <= 16) {
        int p = (bid - 1) * 256 + threadIdx.x;      // < 4096
        int k2 = p >> 6, c2 = p & 63;
        float4 v;
        v.x = W1[(2 * k2) * 128 + 2 * c2];
        v.y = W1[(2 * k2 + 1) * 128 + 2 * c2];
        v.z = W1[(2 * k2) * 128 + 2 * c2 + 1];
        v.w = W1[(2 * k2 + 1) * 128 + 2 * c2 + 1];
        ((float4*)g_W1p)[p] = v;
    } else if (bid <= 24) {
        int p = (bid - 17) * 256 + threadIdx.x;     // < 2048
        int k2 = p >> 5, c2 = p & 31;
        float4 v;
        v.x = W2[(2 * k2) * 64 + 2 * c2];
        v.y = W2[(2 * k2 + 1) * 64 + 2 * c2];
        v.z = W2[(2 * k2) * 64 + 2 * c2 + 1];
        v.w = W2[(2 * k2 + 1) * 64 + 2 * c2 + 1];
        ((float4*)g_W2p)[p] = v;
    }
}

// ---------------------------------------------------------------- count
__global__ void k_count(const int* __restrict__ ei) {
    int e = blockIdx.x * blockDim.x + threadIdx.x;
    if (e < NE) {
        int d = edge_dst(ei, e);
        if (d >= 0 && d < NN) atomicAdd(&g_deg[d], 1);
    }
}

// ---------------------------------------------------------------- scan (+dinv fused)
__global__ void __launch_bounds__(SCAN_B) k_scan_local() {
    __shared__ int wsum[32];
    int tid = threadIdx.x, lane = tid & 31, wid = tid >> 5;
    int gid = blockIdx.x * SCAN_B + tid;
    int v = (gid < NN) ? g_deg[gid] : 0;
    if (gid < NN) g_dinv[gid] = rsqrtf((float)(v + 1));
    int s = v;
#pragma unroll
    for (int o = 1; o < 32; o <<= 1) {
        int t = __shfl_up_sync(0xffffffffu, s, o);
        if (lane >= o) s += t;
    }
    if (lane == 31) wsum[wid] = s;
    __syncthreads();
    if (wid == 0) {
        int ws = wsum[lane];
#pragma unroll
        for (int o = 1; o < 32; o <<= 1) {
            int t = __shfl_up_sync(0xffffffffu, ws, o);
            if (lane >= o) ws += t;
        }
        wsum[lane] = ws;
    }
    __syncthreads();
    int base = (wid > 0) ? wsum[wid - 1] : 0;
    if (gid < NN) g_rowstart[gid] = base + s - v;
    if (tid == SCAN_B - 1) g_blocksum[blockIdx.x] = base + s;
}

__global__ void k_scan_blocks() {
    __shared__ int s[NBLK];
    int tid = threadIdx.x;
    if (tid < NBLK) s[tid] = g_blocksum[tid];
    __syncthreads();
    if (tid == 0) {
        int run = 0;
        for (int i = 0; i < NBLK; i++) { int t = s[i]; s[i] = run; run += t; }
        g_rowstart[NN] = run;
    }
    __syncthreads();
    if (tid < NBLK) g_blocksum[tid] = s[tid];
}

__global__ void __launch_bounds__(SCAN_B) k_scan_add() {
    int gid = blockIdx.x * SCAN_B + threadIdx.x;
    if (gid < NN) g_rowstart[gid] += g_blocksum[blockIdx.x];
}

// ---------------------------------------------------------------- CSR fill
__global__ void k_fill(const int* __restrict__ ei) {
    int e = blockIdx.x * blockDim.x + threadIdx.x;
    if (e >= NE) return;
    int s = edge_src(ei, e);
    int d = edge_dst(ei, e);
    if (s < 0 || s >= NN || d < 0 || d >= NN) return;
    int pos = g_rowstart[d] + atomicAdd(&g_cnt[d], 1);
    g_csr[pos] = s;
}

// ---------------------------------------------------------------- GEMM1 (FFMA2, k-pair, raw)
__global__ void __launch_bounds__(256) k_gemm1_raw(const float* __restrict__ x) {
    extern __shared__ float sm[];
    float* sWp = sm;              // 128*128 (pair-interleaved)
    float* sX  = sm + 128 * 128;  // 64*128
    int tid = threadIdx.x;
    int row0 = blockIdx.x * 64;

    for (int i = tid; i < 128 * 128 / 4; i += 256)
        ((float4*)sWp)[i] = ((const float4*)g_W1p)[i];
    for (int i = tid; i < 64 * 128 / 4; i += 256) {
        int r = i >> 5, gr = row0 + r;
        ((float4*)sX)[i] = (gr < NN) ? ((const float4*)x)[gr * 32 + (i & 31)]
                                     : make_float4(0.f, 0.f, 0.f, 0.f);
    }
    __syncthreads();

    int c = tid & 31;
    int r = tid >> 5;
    ULL acc[8][4];
#pragma unroll
    for (int i = 0; i < 8; i++)
#pragma unroll
        for (int j = 0; j < 4; j++) acc[i][j] = pk2(0.f, 0.f);

#pragma unroll 4
    for (int k2 = 0; k2 < 64; k2++) {
        ulonglong2 wA = ((const ulonglong2*)sWp)[k2 * 64 + c];
        ulonglong2 wB = ((const ulonglong2*)sWp)[k2 * 64 + 32 + c];
#pragma unroll
        for (int i = 0; i < 8; i++) {
            ULL xp = ((const ULL*)sX)[(r + 8 * i) * 64 + k2];
            fma2(acc[i][0], xp, wA.x);
            fma2(acc[i][1], xp, wA.y);
            fma2(acc[i][2], xp, wB.x);
            fma2(acc[i][3], xp, wB.y);
        }
    }

#pragma unroll
    for (int i = 0; i < 8; i++) {
        int gr = row0 + r + 8 * i;
        if (gr < NN) {
            float2 p0 = upk2(acc[i][0]), p1 = upk2(acc[i][1]);
            float2 p2 = upk2(acc[i][2]), p3 = upk2(acc[i][3]);
            ((float2*)g_g1)[gr * 64 + c]      = make_float2(p0.x + p0.y, p1.x + p1.y);
            ((float2*)g_g1)[gr * 64 + 32 + c] = make_float2(p2.x + p2.y, p3.x + p3.y);
        }
    }
}

// ---------------------------------------------------------------- GEMM2 fused with aggregate1
// A-tile rows are computed in-kernel: h1[n] = relu(dinv[n]*(dinv[n]*g1[n] +
// sum_s dinv[s]*g1[s]) + b1), written straight into smem, then FFMA2 GEMM:
// g2 = dinv ⊙ (h1 @ W2).
__global__ void __launch_bounds__(256) k_gemm2f(const float* __restrict__ b1) {
    extern __shared__ float sm[];
    float* sWp = sm;             // 128*64 (pair-interleaved)
    float* sX  = sm + 128 * 64;  // 64*128
    int tid = threadIdx.x;
    int row0 = blockIdx.x * 64;
    int wid = tid >> 5, lane = tid & 31;

    for (int i = tid; i < 128 * 64 / 4; i += 256)
        ((float4*)sWp)[i] = ((const float4*)g_W2p)[i];

    // Gather phase: warp per row, 8 rows per warp (64 rows / 8 warps).
    float4 bv = ((const float4*)b1)[lane];
    for (int rr = wid; rr < 64; rr += 8) {
        int node = row0 + rr;
        float4 o = make_float4(0.f, 0.f, 0.f, 0.f);
        if (node < NN) {
            int beg = g_rowstart[node];
            int end = g_rowstart[node + 1];
            float dn = g_dinv[node];
            float4 sv = ((const float4*)g_g1)[node * 32 + lane];
            float4 acc = make_float4(dn * sv.x, dn * sv.y, dn * sv.z, dn * sv.w);
            int i = beg;
            for (; i + 3 < end; i += 4) {
                int s0 = g_csr[i], s1 = g_csr[i + 1], s2 = g_csr[i + 2], s3 = g_csr[i + 3];
                float d0 = g_dinv[s0], d1 = g_dinv[s1], d2 = g_dinv[s2], d3 = g_dinv[s3];
                float4 v0 = ((const float4*)g_g1)[s0 * 32 + lane];
                float4 v1 = ((const float4*)g_g1)[s1 * 32 + lane];
                float4 v2 = ((const float4*)g_g1)[s2 * 32 + lane];
                float4 v3 = ((const float4*)g_g1)[s3 * 32 + lane];
                acc.x += d0 * v0.x + d1 * v1.x + d2 * v2.x + d3 * v3.x;
                acc.y += d0 * v0.y + d1 * v1.y + d2 * v2.y + d3 * v3.y;
                acc.z += d0 * v0.z + d1 * v1.z + d2 * v2.z + d3 * v3.z;
                acc.w += d0 * v0.w + d1 * v1.w + d2 * v2.w + d3 * v3.w;
            }
            for (; i < end; i++) {
                int s = g_csr[i];
                float d = g_dinv[s];
                float4 v = ((const float4*)g_g1)[s * 32 + lane];
                acc.x += d * v.x; acc.y += d * v.y; acc.z += d * v.z; acc.w += d * v.w;
            }
            o.x = fmaxf(fmaf(dn, acc.x, bv.x), 0.f);
            o.y = fmaxf(fmaf(dn, acc.y, bv.y), 0.f);
            o.z = fmaxf(fmaf(dn, acc.z, bv.z), 0.f);
            o.w = fmaxf(fmaf(dn, acc.w, bv.w), 0.f);
        }
        ((float4*)sX)[rr * 32 + lane] = o;
    }
    __syncthreads();

    int c = tid & 15;
    int r = tid >> 4;
    ULL acc[4][4];
#pragma unroll
    for (int i = 0; i < 4; i++)
#pragma unroll
        for (int j = 0; j < 4; j++) acc[i][j] = pk2(0.f, 0.f);

#pragma unroll 4
    for (int k2 = 0; k2 < 64; k2++) {
        ulonglong2 wA = ((const ulonglong2*)sWp)[k2 * 32 + c];
        ulonglong2 wB = ((const ulonglong2*)sWp)[k2 * 32 + 16 + c];
#pragma unroll
        for (int i = 0; i < 4; i++) {
            ULL xp = ((const ULL*)sX)[(r + 16 * i) * 64 + k2];
            fma2(acc[i][0], xp, wA.x);
            fma2(acc[i][1], xp, wA.y);
            fma2(acc[i][2], xp, wB.x);
            fma2(acc[i][3], xp, wB.y);
        }
    }

#pragma unroll
    for (int i = 0; i < 4; i++) {
        int gr = row0 + r + 16 * i;
        if (gr < NN) {
            float s = g_dinv[gr];
            float2 p0 = upk2(acc[i][0]), p1 = upk2(acc[i][1]);
            float2 p2 = upk2(acc[i][2]), p3 = upk2(acc[i][3]);
            ((float2*)g_g2)[gr * 32 + c]      = make_float2(s * (p0.x + p0.y), s * (p1.x + p1.y));
            ((float2*)g_g2)[gr * 32 + 16 + c] = make_float2(s * (p2.x + p2.y), s * (p3.x + p3.y));
        }
    }
}

// ---------------------------------------------------------------- aggregate2
__global__ void __launch_bounds__(256) k_agg2(const float* __restrict__ b2,
                                              float* __restrict__ out) {
    int t = blockIdx.x * 256 + threadIdx.x;
    int node = t >> 4;
    int l = t & 15;
    if (node >= NN) return;
    int beg = g_rowstart[node];
    int end = g_rowstart[node + 1];
    float4 acc = ((const float4*)g_g2)[node * 16 + l];
    int i = beg;
    for (; i + 3 < end; i += 4) {
        int s0 = g_csr[i], s1 = g_csr[i + 1], s2 = g_csr[i + 2], s3 = g_csr[i + 3];
        float4 v0 = ((const float4*)g_g2)[s0 * 16 + l];
        float4 v1 = ((const float4*)g_g2)[s1 * 16 + l];
        float4 v2 = ((const float4*)g_g2)[s2 * 16 + l];
        float4 v3 = ((const float4*)g_g2)[s3 * 16 + l];
        acc.x += v0.x + v1.x + v2.x + v3.x;
        acc.y += v0.y + v1.y + v2.y + v3.y;
        acc.z += v0.z + v1.z + v2.z + v3.z;
        acc.w += v0.w + v1.w + v2.w + v3.w;
    }
    for (; i < end; i++) {
        float4 v = ((const float4*)g_g2)[g_csr[i] * 16 + l];
        acc.x += v.x; acc.y += v.y; acc.z += v.z; acc.w += v.w;
    }
    float dn = g_dinv[node];
    float4 o;
    o.x = fmaf(dn, acc.x, __ldg(&b2[l * 4 + 0]));
    o.y = fmaf(dn, acc.y, __ldg(&b2[l * 4 + 1]));
    o.z = fmaf(dn, acc.z, __ldg(&b2[l * 4 + 2]));
    o.w = fmaf(dn, acc.w, __ldg(&b2[l * 4 + 3]));
    ((float4*)out)[node * 16 + l] = o;
}

// ----------------------------------------------------------------
extern "C" void kernel_launch(void* const* d_in, const int* in_sizes, int n_in,
                              void* d_out, int out_size) {
    const float* x  = (const float*)d_in[0];
    const int*   ei = (const int*)d_in[1];
    const float* W1 = (const float*)d_in[2];
    const float* b1 = (const float*)d_in[3];
    const float* W2 = (const float*)d_in[4];
    const float* b2 = (const float*)d_in[5];
    float* out = (float*)d_out;

    const int smem1 = (128 * 128 + 64 * 128) * 4;  // 96 KB
    const int smem2 = (128 * 64 + 64 * 128) * 4;   // 64 KB
    cudaFuncSetAttribute(k_gemm1_raw, cudaFuncAttributeMaxDynamicSharedMemorySize, smem1);
    cudaFuncSetAttribute(k_gemm2f,    cudaFuncAttributeMaxDynamicSharedMemorySize, smem2);

    // Fork a second stream so the edge-prep chain overlaps GEMM1.
    cudaStream_t s2;
    cudaEvent_t evA, evB;
    cudaStreamCreateWithFlags(&s2, cudaStreamNonBlocking);
    cudaEventCreateWithFlags(&evA, cudaEventDisableTiming);
    cudaEventCreateWithFlags(&evB, cudaEventDisableTiming);

    k_pre<<<(NN + 255) / 256, 256>>>(ei, W1, W2);

    cudaEventRecord(evA, 0);
    cudaStreamWaitEvent(s2, evA, 0);

    // prep chain on s2 (independent of GEMM1)
    k_count<<<(NE + 255) / 256, 256, 0, s2>>>(ei);
    k_scan_local <<<NBLK, SCAN_B, 0, s2>>>();
    k_scan_blocks<<<1, 128, 0, s2>>>();
    k_scan_add   <<<NBLK, SCAN_B, 0, s2>>>();
    k_fill<<<(NE + 255) / 256, 256, 0, s2>>>(ei);
    cudaEventRecord(evB, s2);

    // GEMM1 on main stream, concurrent with prep
    k_gemm1_raw<<<(NN + 63) / 64, 256, smem1>>>(x);

    cudaStreamWaitEvent(0, evB, 0);   // join

    k_gemm2f<<<(NN + 63) / 64, 256, smem2>>>(b1);   // agg1 fused into A-tile load
    k_agg2  <<<(NN * 16 + 255) / 256, 256>>>(b2, out);

    cudaEventDestroy(evA);
    cudaEventDestroy(evB);
    cudaStreamDestroy(s2);
}